// round 10
// baseline (speedup 1.0000x reference)
#include <cuda_runtime.h>
#include <cuda_bf16.h>

#define MAX_NODES 50000
#define MAX_E     800000
#define F 128
#define DEG_CAP   64
#define SPILL_CAP 65536

// Scratch (device globals; allocation-free per harness rules)
__device__ float g_agg[MAX_NODES * F];
__device__ float g_h[MAX_NODES * F];
__device__ float g_stats[2 * F];       // [0:128) sum, [128:256) sumsq
__device__ float g_sc[F];              // BN scale folded into W2 columns
__device__ float g_b2p[F];             // BN-folded bias for layer 2
__device__ int   g_cnt[MAX_NODES];     // degree per dst
__device__ int   g_csrp[MAX_NODES * DEG_CAP];  // padded CSR (12.8 MB)
__device__ int   g_spill[2 * SPILL_CAP];
__device__ int   g_nspill;
__device__ int   g_is64;

// ---------------------------------------------------------------------------
// tf32 helpers
// ---------------------------------------------------------------------------
__device__ __forceinline__ unsigned tf32r(float f) {
    unsigned u;
    asm("cvt.rna.tf32.f32 %0, %1;" : "=r"(u) : "f"(f));
    return u;
}
__device__ __forceinline__ void mma_tf32(
    float& d0, float& d1, float& d2, float& d3,
    unsigned a0, unsigned a1, unsigned a2, unsigned a3,
    unsigned b0, unsigned b1) {
    asm volatile(
        "mma.sync.aligned.m16n8k8.row.col.f32.tf32.tf32.f32 "
        "{%0,%1,%2,%3},{%4,%5,%6,%7},{%8,%9},{%0,%1,%2,%3};"
        : "+f"(d0), "+f"(d1), "+f"(d2), "+f"(d3)
        : "r"(a0), "r"(a1), "r"(a2), "r"(a3), "r"(b0), "r"(b1));
}

// ---------------------------------------------------------------------------
// zero: counters + BN stats + spill count; block 0 warp 0 also detects the
// edge_index dtype (int64 <=> all odd 32-bit words zero).
// ---------------------------------------------------------------------------
__global__ void zero_kernel(const int* __restrict__ ei, int n_words,
                            int n_nodes) {
    if (blockIdx.x == 0 && threadIdx.x < 32) {
        int nz = 0;
        for (int i = threadIdx.x; i < 2048; i += 32) {
            int w = 2 * i + 1;
            if (w < n_words && ei[w] != 0) nz = 1;
        }
        nz = __any_sync(0xffffffffu, nz);
        if (threadIdx.x == 0) g_is64 = nz ? 0 : 1;
    }
    int i = blockIdx.x * blockDim.x + threadIdx.x;
    if (i < n_nodes) g_cnt[i] = 0;
    if (i < 2 * F) g_stats[i] = 0.0f;
    if (i == 2 * F) g_nspill = 0;
}

// ---------------------------------------------------------------------------
// convert: unpack indices (guarded) + build padded CSR directly
// ---------------------------------------------------------------------------
__global__ void convert_kernel(const void* __restrict__ eiv, int n_edges,
                               int n_nodes) {
    int e = blockIdx.x * blockDim.x + threadIdx.x;
    if (e >= n_edges) return;
    long long s, d;
    if (g_is64) {
        const long long* ei = (const long long*)eiv;
        s = ei[e];
        d = ei[n_edges + e];
    } else {
        const int* ei = (const int*)eiv;
        s = ei[e];
        d = ei[n_edges + e];
    }
    if (s < 0 || s >= n_nodes || d < 0 || d >= n_nodes) return;
    int di = (int)d, si = (int)s;
    int c = atomicAdd(&g_cnt[di], 1);
    if (c < DEG_CAP) {
        g_csrp[di * DEG_CAP + c] = si;
    } else {
        int p = atomicAdd(&g_nspill, 1);
        if (p < SPILL_CAP) {
            g_spill[2 * p] = di;
            g_spill[2 * p + 1] = si;
        }
    }
}

// ---------------------------------------------------------------------------
// gather: agg[m] = x[m] + sum_{src in CSR[m]} x[src]; one warp per node.
// ---------------------------------------------------------------------------
__device__ __forceinline__ void f4add(float4& a, const float4& b) {
    a.x += b.x; a.y += b.y; a.z += b.z; a.w += b.w;
}

__global__ void __launch_bounds__(256)
gather_kernel(const float* __restrict__ Xp, int n_nodes) {
    int m = (blockIdx.x * blockDim.x + threadIdx.x) >> 5;
    int tx = threadIdx.x & 31;
    if (m >= n_nodes) return;
    const float4* x4 = (const float4*)Xp;

    float4 a0 = __ldg(&x4[(size_t)m * 32 + tx]);   // self term
    float4 a1 = make_float4(0.f, 0.f, 0.f, 0.f);
    float4 a2 = a1, a3 = a1;

    int deg = g_cnt[m];
    int dc = deg < DEG_CAP ? deg : DEG_CAP;
    const int* lst = g_csrp + (size_t)m * DEG_CAP;
    int e = 0;
    for (; e + 3 < dc; e += 4) {
        int s0 = __ldg(&lst[e]),     s1 = __ldg(&lst[e + 1]);
        int s2 = __ldg(&lst[e + 2]), s3 = __ldg(&lst[e + 3]);
        float4 v0 = __ldg(&x4[(size_t)s0 * 32 + tx]);
        float4 v1 = __ldg(&x4[(size_t)s1 * 32 + tx]);
        float4 v2 = __ldg(&x4[(size_t)s2 * 32 + tx]);
        float4 v3 = __ldg(&x4[(size_t)s3 * 32 + tx]);
        f4add(a0, v0); f4add(a1, v1); f4add(a2, v2); f4add(a3, v3);
    }
    for (; e < dc; e++)
        f4add(a1, __ldg(&x4[(size_t)__ldg(&lst[e]) * 32 + tx]));
    if (deg > DEG_CAP) {                 // spill path (normally never taken)
        int nspill = g_nspill;
        if (nspill > SPILL_CAP) nspill = SPILL_CAP;
        for (int q = 0; q < nspill; q++)
            if (g_spill[2 * q] == m)
                f4add(a2, __ldg(&x4[(size_t)g_spill[2 * q + 1] * 32 + tx]));
    }
    f4add(a0, a1); f4add(a2, a3); f4add(a0, a2);
    ((float4*)g_agg)[(size_t)m * 32 + tx] = a0;
}

// ---------------------------------------------------------------------------
// Tensor-core GEMM (tf32 mma.sync): out[m][n] = act(sum_k A[m][k]*W[n][k]+b)
// Block: 256 thr = 8 warps (wy 2 x wx 4); tile 64(m) x 128(n), K=128.
// k-pair-INTERLEAVED smem layout: within each k8 group, k is stored at column
// 2*(k&3) + (k>>2), so a thread's fragment pair (k=tig, k=tig+4) is adjacent
// -> every fragment load is one LDS.64. PITCH=136 makes the 8B-unit bank
// index (4g+tig) mod 16 -> conflict-free per half-warp phase.
// FIRST: A=g_agg, ReLU + BN stats, out=g_h.
// else:  A=g_h, W cols scaled by g_sc, bias=g_b2p, out=d_out.
// ---------------------------------------------------------------------------
#define PITCH 136
#define GEMM_SMEM ((64 + 128) * PITCH * 4)

__device__ __forceinline__ void store_interleaved(float* dst, float4 lo,
                                                  float4 hi) {
    // lo = k 0..3 of a k8 group, hi = k 4..7; permuted cols:
    // c'={0..7} <-> k={0,4,1,5,2,6,3,7}
    uint4 u0 = make_uint4(tf32r(lo.x), tf32r(hi.x), tf32r(lo.y), tf32r(hi.y));
    uint4 u1 = make_uint4(tf32r(lo.z), tf32r(hi.z), tf32r(lo.w), tf32r(hi.w));
    *(uint4*)dst = u0;
    *(uint4*)(dst + 4) = u1;
}

template <bool FIRST>
__global__ void __launch_bounds__(256, 2)
gemm_kernel(const float* __restrict__ Wp, const float* __restrict__ biasp,
            float* __restrict__ outp, int M) {
    extern __shared__ float smem[];
    float* As = smem;               // 64 x PITCH (tf32, k-interleaved)
    float* Ws = smem + 64 * PITCH;  // 128 x PITCH (tf32, k-interleaved)

    const float* A    = FIRST ? g_agg : g_h;
    const float* bias = FIRST ? biasp : g_b2p;
    float* out        = FIRST ? g_h   : outp;

    int tid = threadIdx.x;
    int lane = tid & 31, wid = tid >> 5;
    int g = lane >> 2, tig = lane & 3;
    int wy = wid & 1, wx = wid >> 1;
    int m0 = blockIdx.x * 64;

    // Load W (128 rows x 16 k8-groups), interleave+round, store pitch-136.
#pragma unroll
    for (int p = 0; p < 8; p++) {
        int idx = tid + p * 256;
        int r = idx >> 4, gno = idx & 15;
        const float4* src = (const float4*)Wp + (size_t)r * 32 + gno * 2;
        float4 lo = src[0], hi = src[1];
        if (!FIRST) {
            float4 sl = ((const float4*)g_sc)[gno * 2];
            float4 sh = ((const float4*)g_sc)[gno * 2 + 1];
            lo.x *= sl.x; lo.y *= sl.y; lo.z *= sl.z; lo.w *= sl.w;
            hi.x *= sh.x; hi.y *= sh.y; hi.z *= sh.z; hi.w *= sh.w;
        }
        store_interleaved(&Ws[r * PITCH + gno * 8], lo, hi);
    }
    // Load A tile (64 rows x 16 k8-groups)
#pragma unroll
    for (int p = 0; p < 4; p++) {
        int idx = tid + p * 256;
        int r = idx >> 4, gno = idx & 15;
        int m = m0 + r;
        float4 lo = make_float4(0.f, 0.f, 0.f, 0.f), hi = lo;
        if (m < M) {
            const float4* src = (const float4*)A + (size_t)m * 32 + gno * 2;
            lo = src[0]; hi = src[1];
        }
        store_interleaved(&As[r * PITCH + gno * 8], lo, hi);
    }
    __syncthreads();

    float d[2][4][4];
#pragma unroll
    for (int mi = 0; mi < 2; mi++)
#pragma unroll
        for (int ni = 0; ni < 4; ni++)
#pragma unroll
            for (int j = 0; j < 4; j++) d[mi][ni][j] = 0.0f;

    const float* Ab = As + (wy * 32) * PITCH + 2 * tig;
    const float* Bb = Ws + (wx * 32) * PITCH + 2 * tig;

#pragma unroll
    for (int kk = 0; kk < 16; kk++) {
        int kc = kk * 8;
        uint2 alo[2], ahi[2];          // alo: row g (k tig, tig+4); ahi: row g+8
#pragma unroll
        for (int mi = 0; mi < 2; mi++) {
            const float* ap = Ab + (mi * 16 + g) * PITCH + kc;
            alo[mi] = *(const uint2*)ap;
            ahi[mi] = *(const uint2*)(ap + 8 * PITCH);
        }
        uint2 b[4];
#pragma unroll
        for (int ni = 0; ni < 4; ni++)
            b[ni] = *(const uint2*)(Bb + (ni * 8 + g) * PITCH + kc);
#pragma unroll
        for (int mi = 0; mi < 2; mi++)
#pragma unroll
            for (int ni = 0; ni < 4; ni++)
                mma_tf32(d[mi][ni][0], d[mi][ni][1], d[mi][ni][2], d[mi][ni][3],
                         alo[mi].x, ahi[mi].x, alo[mi].y, ahi[mi].y,
                         b[ni].x, b[ni].y);
    }
    __syncthreads();  // smem reused for stats staging below

    // Epilogue: bias (+ReLU+stats for FIRST), write out.
    float pS[4][2], pQ[4][2];
#pragma unroll
    for (int ni = 0; ni < 4; ni++) {
        pS[ni][0] = pS[ni][1] = 0.f;
        pQ[ni][0] = pQ[ni][1] = 0.f;
    }
#pragma unroll
    for (int mi = 0; mi < 2; mi++) {
        int r0 = m0 + wy * 32 + mi * 16 + g;
        int r1 = r0 + 8;
#pragma unroll
        for (int ni = 0; ni < 4; ni++) {
            int c = wx * 32 + ni * 8 + 2 * tig;
            float b0 = bias[c], b1 = bias[c + 1];
            if (r0 < M) {
                float v0 = d[mi][ni][0] + b0;
                float v1 = d[mi][ni][1] + b1;
                if (FIRST) { v0 = fmaxf(v0, 0.f); v1 = fmaxf(v1, 0.f); }
                *(float2*)&out[(size_t)r0 * F + c] = make_float2(v0, v1);
                if (FIRST) {
                    pS[ni][0] += v0; pS[ni][1] += v1;
                    pQ[ni][0] += v0 * v0; pQ[ni][1] += v1 * v1;
                }
            }
            if (r1 < M) {
                float v0 = d[mi][ni][2] + b0;
                float v1 = d[mi][ni][3] + b1;
                if (FIRST) { v0 = fmaxf(v0, 0.f); v1 = fmaxf(v1, 0.f); }
                *(float2*)&out[(size_t)r1 * F + c] = make_float2(v0, v1);
                if (FIRST) {
                    pS[ni][0] += v0; pS[ni][1] += v1;
                    pQ[ni][0] += v0 * v0; pQ[ni][1] += v1 * v1;
                }
            }
        }
    }

    if (FIRST) {
        // Reduce over g via shfl (lanes differing in bits 2..4), stage
        // per-(wy,col) partials in smem, then 256 global atomics.
#pragma unroll
        for (int ni = 0; ni < 4; ni++)
#pragma unroll
            for (int j = 0; j < 2; j++) {
#pragma unroll
                for (int mask = 4; mask <= 16; mask <<= 1) {
                    pS[ni][j] += __shfl_xor_sync(0xffffffffu, pS[ni][j], mask);
                    pQ[ni][j] += __shfl_xor_sync(0xffffffffu, pQ[ni][j], mask);
                }
            }
        float* sS = smem;          // [2][128]
        float* sQ = smem + 256;    // [2][128]
        if (g == 0) {
#pragma unroll
            for (int ni = 0; ni < 4; ni++) {
                int c = wx * 32 + ni * 8 + 2 * tig;
                sS[wy * F + c]     = pS[ni][0];
                sS[wy * F + c + 1] = pS[ni][1];
                sQ[wy * F + c]     = pQ[ni][0];
                sQ[wy * F + c + 1] = pQ[ni][1];
            }
        }
        __syncthreads();
        if (tid < F)
            atomicAdd(&g_stats[tid], sS[tid] + sS[F + tid]);
        else if (tid < 2 * F) {
            int c = tid - F;
            atomicAdd(&g_stats[F + c], sQ[c] + sQ[F + c]);
        }
    }
}

// ---------------------------------------------------------------------------
// fold: s[k] = gamma*rsqrt(var+eps), t[k] = beta - mean*s
//   g_sc[k] = s[k]  (applied to W2 columns inside gemm2's W load)
//   g_b2p[o] = b2[o] + sum_k W2[o][k] * t[k]     (one block per row o)
// ---------------------------------------------------------------------------
__global__ void fold_kernel(const float* __restrict__ gamma,
                            const float* __restrict__ beta,
                            const float* __restrict__ W2,
                            const float* __restrict__ b2, float invM) {
    __shared__ float red[F];
    int o = blockIdx.x, t = threadIdx.x;  // 128 blocks x 128 threads
    float S = g_stats[t], Q = g_stats[F + t];
    float mean = S * invM;
    float var = Q * invM - mean * mean;
    float s = gamma[t] * rsqrtf(var + 1e-5f);
    float tc = beta[t] - mean * s;
    if (o == 0) g_sc[t] = s;
    red[t] = W2[o * F + t] * tc;
    __syncthreads();
#pragma unroll
    for (int off = 64; off > 0; off >>= 1) {
        if (t < off) red[t] += red[t + off];
        __syncthreads();
    }
    if (t == 0) g_b2p[o] = b2[o] + red[0];
}

// ---------------------------------------------------------------------------
extern "C" void kernel_launch(void* const* d_in, const int* in_sizes, int n_in,
                              void* d_out, int out_size) {
    const float* x         = (const float*)d_in[0];
    const void*  ei        = (const void*)d_in[1];
    const float* W1        = (const float*)d_in[2];
    const float* b1        = (const float*)d_in[3];
    const float* gamma     = (const float*)d_in[4];
    const float* beta      = (const float*)d_in[5];
    const float* W2        = (const float*)d_in[6];
    const float* b2        = (const float*)d_in[7];
    float* out             = (float*)d_out;

    int n_nodes = in_sizes[0] / F;
    int n_edges = in_sizes[1] / 2;

    cudaFuncSetAttribute(gemm_kernel<true>,
                         cudaFuncAttributeMaxDynamicSharedMemorySize, GEMM_SMEM);
    cudaFuncSetAttribute(gemm_kernel<false>,
                         cudaFuncAttributeMaxDynamicSharedMemorySize, GEMM_SMEM);

    zero_kernel<<<(n_nodes + 255) / 256, 256>>>((const int*)ei, in_sizes[1],
                                                n_nodes);
    convert_kernel<<<(n_edges + 255) / 256, 256>>>(ei, n_edges, n_nodes);

    int gwarps_blocks = (n_nodes * 32 + 255) / 256;
    gather_kernel<<<gwarps_blocks, 256>>>(x, n_nodes);

    int gb = (n_nodes + 63) / 64;
    gemm_kernel<true><<<gb, 256, GEMM_SMEM>>>(W1, b1, nullptr, n_nodes);
    fold_kernel<<<F, F>>>(gamma, beta, W2, b2, 1.0f / (float)n_nodes);
    gemm_kernel<false><<<gb, 256, GEMM_SMEM>>>(W2, nullptr, out, n_nodes);
}

// round 11
// speedup vs baseline: 1.1244x; 1.1244x over previous
#include <cuda_runtime.h>
#include <cuda_bf16.h>

#define MAX_NODES 50000
#define MAX_E     800000
#define F 128
#define DEG_CAP   64
#define SPILL_CAP 65536

// Scratch (device globals; allocation-free per harness rules)
__device__ __align__(16) float g_agg[MAX_NODES * F];   // tf32-rounded agg
__device__ __align__(16) float g_h[MAX_NODES * F];     // tf32-rounded hidden
__device__ __align__(16) float g_W1p[F * F];           // tf32-rounded W1
__device__ __align__(16) float g_W2p[F * F];           // BN-scaled, rounded W2
__device__ float g_stats[2 * F];       // [0:128) sum, [128:256) sumsq
__device__ float g_b2p[F];             // BN-folded bias for layer 2
__device__ int   g_cnt[MAX_NODES];     // degree per dst
__device__ int   g_csrp[MAX_NODES * DEG_CAP];  // padded CSR (12.8 MB)
__device__ int   g_spill[2 * SPILL_CAP];
__device__ int   g_nspill;
__device__ int   g_is64;

// ---------------------------------------------------------------------------
// tf32 / mma / cp.async helpers
// ---------------------------------------------------------------------------
__device__ __forceinline__ unsigned tf32r(float f) {
    unsigned u;
    asm("cvt.rna.tf32.f32 %0, %1;" : "=r"(u) : "f"(f));
    return u;
}
__device__ __forceinline__ float tf32rf(float f) {
    return __uint_as_float(tf32r(f));
}
__device__ __forceinline__ void mma_tf32(
    float& d0, float& d1, float& d2, float& d3,
    unsigned a0, unsigned a1, unsigned a2, unsigned a3,
    unsigned b0, unsigned b1) {
    asm volatile(
        "mma.sync.aligned.m16n8k8.row.col.f32.tf32.tf32.f32 "
        "{%0,%1,%2,%3},{%4,%5,%6,%7},{%8,%9},{%0,%1,%2,%3};"
        : "+f"(d0), "+f"(d1), "+f"(d2), "+f"(d3)
        : "r"(a0), "r"(a1), "r"(a2), "r"(a3), "r"(b0), "r"(b1));
}
__device__ __forceinline__ void cp16(float* dst, const float* src, bool valid) {
    unsigned sdst = (unsigned)__cvta_generic_to_shared(dst);
    int sz = valid ? 16 : 0;
    asm volatile("cp.async.ca.shared.global [%0], [%1], 16, %2;"
                 :: "r"(sdst), "l"(src), "r"(sz));
}
__device__ __forceinline__ void cp_commit() {
    asm volatile("cp.async.commit_group;" ::: "memory");
}

// ---------------------------------------------------------------------------
// zero: counters + stats + spill; block0/warp0 detects edge dtype;
// blocks [0,64) also prep tf32-rounded W1 -> g_W1p.
// ---------------------------------------------------------------------------
__global__ void zero_kernel(const int* __restrict__ ei, int n_words,
                            int n_nodes, const float* __restrict__ W1) {
    if (blockIdx.x == 0 && threadIdx.x < 32) {
        int nz = 0;
        for (int i = threadIdx.x; i < 2048; i += 32) {
            int w = 2 * i + 1;
            if (w < n_words && ei[w] != 0) nz = 1;
        }
        nz = __any_sync(0xffffffffu, nz);
        if (threadIdx.x == 0) g_is64 = nz ? 0 : 1;
    }
    if (blockIdx.x < 64) {
        int r = blockIdx.x * 2 + (threadIdx.x >> 7);
        int c = threadIdx.x & 127;
        g_W1p[r * F + c] = tf32rf(W1[r * F + c]);
    }
    int i = blockIdx.x * blockDim.x + threadIdx.x;
    if (i < n_nodes) g_cnt[i] = 0;
    if (i < 2 * F) g_stats[i] = 0.0f;
    if (i == 2 * F) g_nspill = 0;
}

// ---------------------------------------------------------------------------
// convert: unpack indices (guarded) + build padded CSR directly
// ---------------------------------------------------------------------------
__global__ void convert_kernel(const void* __restrict__ eiv, int n_edges,
                               int n_nodes) {
    int e = blockIdx.x * blockDim.x + threadIdx.x;
    if (e >= n_edges) return;
    long long s, d;
    if (g_is64) {
        const long long* ei = (const long long*)eiv;
        s = ei[e];
        d = ei[n_edges + e];
    } else {
        const int* ei = (const int*)eiv;
        s = ei[e];
        d = ei[n_edges + e];
    }
    if (s < 0 || s >= n_nodes || d < 0 || d >= n_nodes) return;
    int di = (int)d, si = (int)s;
    int c = atomicAdd(&g_cnt[di], 1);
    if (c < DEG_CAP) {
        g_csrp[di * DEG_CAP + c] = si;
    } else {
        int p = atomicAdd(&g_nspill, 1);
        if (p < SPILL_CAP) {
            g_spill[2 * p] = di;
            g_spill[2 * p + 1] = si;
        }
    }
}

// ---------------------------------------------------------------------------
// gather: agg[m] = x[m] + sum_{src in CSR[m]} x[src]; one warp per node.
// Output is tf32-rounded (gemm1 consumes it raw via cp.async).
// ---------------------------------------------------------------------------
__device__ __forceinline__ void f4add(float4& a, const float4& b) {
    a.x += b.x; a.y += b.y; a.z += b.z; a.w += b.w;
}

__global__ void __launch_bounds__(256)
gather_kernel(const float* __restrict__ Xp, int n_nodes) {
    int m = (blockIdx.x * blockDim.x + threadIdx.x) >> 5;
    int tx = threadIdx.x & 31;
    if (m >= n_nodes) return;
    const float4* x4 = (const float4*)Xp;

    float4 a0 = __ldg(&x4[(size_t)m * 32 + tx]);   // self term
    float4 a1 = make_float4(0.f, 0.f, 0.f, 0.f);
    float4 a2 = a1, a3 = a1;

    int deg = g_cnt[m];
    int dc = deg < DEG_CAP ? deg : DEG_CAP;
    const int* lst = g_csrp + (size_t)m * DEG_CAP;
    int e = 0;
    for (; e + 3 < dc; e += 4) {
        int s0 = __ldg(&lst[e]),     s1 = __ldg(&lst[e + 1]);
        int s2 = __ldg(&lst[e + 2]), s3 = __ldg(&lst[e + 3]);
        float4 v0 = __ldg(&x4[(size_t)s0 * 32 + tx]);
        float4 v1 = __ldg(&x4[(size_t)s1 * 32 + tx]);
        float4 v2 = __ldg(&x4[(size_t)s2 * 32 + tx]);
        float4 v3 = __ldg(&x4[(size_t)s3 * 32 + tx]);
        f4add(a0, v0); f4add(a1, v1); f4add(a2, v2); f4add(a3, v3);
    }
    for (; e < dc; e++)
        f4add(a1, __ldg(&x4[(size_t)__ldg(&lst[e]) * 32 + tx]));
    if (deg > DEG_CAP) {                 // spill path (normally never taken)
        int nspill = g_nspill;
        if (nspill > SPILL_CAP) nspill = SPILL_CAP;
        for (int q = 0; q < nspill; q++)
            if (g_spill[2 * q] == m)
                f4add(a2, __ldg(&x4[(size_t)g_spill[2 * q + 1] * 32 + tx]));
    }
    f4add(a0, a1); f4add(a2, a3); f4add(a0, a2);
    a0.x = tf32rf(a0.x); a0.y = tf32rf(a0.y);
    a0.z = tf32rf(a0.z); a0.w = tf32rf(a0.w);
    ((float4*)g_agg)[(size_t)m * 32 + tx] = a0;
}

// ---------------------------------------------------------------------------
// Persistent tensor-core GEMM (tf32 mma.sync), cp.async double-buffered A.
// Grid = #SMs, 1 CTA/SM. W (128x128, pre-rounded) loaded to smem ONCE;
// loop over m-tiles (64 rows each) with 2-stage A pipeline.
// Block: 256 thr = 8 warps (wy 2 x wx 4); warp tile 32x32; 16 k-steps of 8.
// FIRST: A=g_agg, W=g_W1p, bias=b1 arg; out=g_h (tf32-rounded) + BN stats.
// else:  A=g_h, W=g_W2p, bias=g_b2p; out=d_out (fp32).
// ---------------------------------------------------------------------------
#define PITCH 132
// floats: W 128*132=16896 | A0 64*132=8448 | A1 8448 | stats 512
#define OFF_A0 16896
#define OFF_A1 25344
#define OFF_ST 33792
#define GEMM_SMEM ((33792 + 512) * 4)

__device__ __forceinline__ void load_W_async(float* Ws, const float* Wsrc,
                                             int tid) {
#pragma unroll
    for (int p = 0; p < 16; p++) {
        int idx = tid + p * 256;          // 16B-granule index (4096 total)
        int r = idx >> 5, c = idx & 31;
        cp16(Ws + r * PITCH + c * 4, Wsrc + r * F + c * 4, true);
    }
}
__device__ __forceinline__ void load_A_async(float* Ab, const float* Asrc,
                                             int m0, int M, int tid) {
#pragma unroll
    for (int p = 0; p < 8; p++) {
        int idx = tid + p * 256;          // 2048 granules
        int r = idx >> 5, c = idx & 31;
        bool v = (m0 + r) < M;
        const float* src = Asrc + (size_t)(v ? m0 + r : 0) * F + c * 4;
        cp16(Ab + r * PITCH + c * 4, src, v);
    }
}

template <bool FIRST>
__global__ void __launch_bounds__(256, 1)
gemm_kernel(const float* __restrict__ biasp, float* __restrict__ outp,
            int M, int ntiles) {
    extern __shared__ float smem[];
    float* Ws = smem;
    float* Abuf[2] = {smem + OFF_A0, smem + OFF_A1};
    float* sS = smem + OFF_ST;          // [2][128]
    float* sQ = smem + OFF_ST + 256;    // [2][128]

    const float* A    = FIRST ? g_agg : g_h;
    const float* Wsrc = FIRST ? g_W1p : g_W2p;
    const float* bias = FIRST ? biasp : g_b2p;
    float* out        = FIRST ? g_h   : outp;

    int tid = threadIdx.x;
    int lane = tid & 31, wid = tid >> 5;
    int g = lane >> 2, tig = lane & 3;
    int wy = wid & 1, wx = wid >> 1;

    // Prologue: W + first A tile in one group
    load_W_async(Ws, Wsrc, tid);
    int t0 = blockIdx.x;
    if (t0 < ntiles) load_A_async(Abuf[0], A, t0 * 64, M, tid);
    cp_commit();

    int buf = 0;
    for (int t = t0; t < ntiles; t += gridDim.x) {
        int tn = t + gridDim.x;
        bool hasNext = tn < ntiles;
        if (hasNext) {
            load_A_async(Abuf[buf ^ 1], A, tn * 64, M, tid);
            cp_commit();
            asm volatile("cp.async.wait_group 1;" ::: "memory");
        } else {
            asm volatile("cp.async.wait_group 0;" ::: "memory");
        }
        __syncthreads();

        int m0 = t * 64;
        float* As = Abuf[buf];

        float d[2][4][4];
#pragma unroll
        for (int mi = 0; mi < 2; mi++)
#pragma unroll
            for (int ni = 0; ni < 4; ni++)
#pragma unroll
                for (int j = 0; j < 4; j++) d[mi][ni][j] = 0.0f;

        const float* Ab = As + (wy * 32) * PITCH;
        const float* Bb = Ws + (wx * 32) * PITCH;

#pragma unroll
        for (int kk = 0; kk < 16; kk++) {
            int kc = kk * 8;
            unsigned a[2][4];
#pragma unroll
            for (int mi = 0; mi < 2; mi++) {
                const float* ap = Ab + (mi * 16 + g) * PITCH + kc + tig;
                a[mi][0] = __float_as_uint(ap[0]);
                a[mi][1] = __float_as_uint(ap[8 * PITCH]);
                a[mi][2] = __float_as_uint(ap[4]);
                a[mi][3] = __float_as_uint(ap[8 * PITCH + 4]);
            }
            unsigned b[4][2];
#pragma unroll
            for (int ni = 0; ni < 4; ni++) {
                const float* bp = Bb + (ni * 8 + g) * PITCH + kc + tig;
                b[ni][0] = __float_as_uint(bp[0]);
                b[ni][1] = __float_as_uint(bp[4]);
            }
#pragma unroll
            for (int mi = 0; mi < 2; mi++)
#pragma unroll
                for (int ni = 0; ni < 4; ni++)
                    mma_tf32(d[mi][ni][0], d[mi][ni][1], d[mi][ni][2],
                             d[mi][ni][3],
                             a[mi][0], a[mi][1], a[mi][2], a[mi][3],
                             b[ni][0], b[ni][1]);
        }

        // Epilogue
        float pS[4][2], pQ[4][2];
#pragma unroll
        for (int ni = 0; ni < 4; ni++) {
            pS[ni][0] = pS[ni][1] = 0.f;
            pQ[ni][0] = pQ[ni][1] = 0.f;
        }
#pragma unroll
        for (int mi = 0; mi < 2; mi++) {
            int r0 = m0 + wy * 32 + mi * 16 + g;
            int r1 = r0 + 8;
#pragma unroll
            for (int ni = 0; ni < 4; ni++) {
                int c = wx * 32 + ni * 8 + 2 * tig;
                float b0 = bias[c], b1 = bias[c + 1];
                if (r0 < M) {
                    float v0 = d[mi][ni][0] + b0;
                    float v1 = d[mi][ni][1] + b1;
                    if (FIRST) {
                        v0 = fmaxf(v0, 0.f); v1 = fmaxf(v1, 0.f);
                        pS[ni][0] += v0; pS[ni][1] += v1;
                        pQ[ni][0] += v0 * v0; pQ[ni][1] += v1 * v1;
                        *(float2*)&out[(size_t)r0 * F + c] =
                            make_float2(tf32rf(v0), tf32rf(v1));
                    } else {
                        *(float2*)&out[(size_t)r0 * F + c] =
                            make_float2(v0, v1);
                    }
                }
                if (r1 < M) {
                    float v0 = d[mi][ni][2] + b0;
                    float v1 = d[mi][ni][3] + b1;
                    if (FIRST) {
                        v0 = fmaxf(v0, 0.f); v1 = fmaxf(v1, 0.f);
                        pS[ni][0] += v0; pS[ni][1] += v1;
                        pQ[ni][0] += v0 * v0; pQ[ni][1] += v1 * v1;
                        *(float2*)&out[(size_t)r1 * F + c] =
                            make_float2(tf32rf(v0), tf32rf(v1));
                    } else {
                        *(float2*)&out[(size_t)r1 * F + c] =
                            make_float2(v0, v1);
                    }
                }
            }
        }

        if (FIRST) {
#pragma unroll
            for (int ni = 0; ni < 4; ni++)
#pragma unroll
                for (int j = 0; j < 2; j++) {
#pragma unroll
                    for (int mask = 4; mask <= 16; mask <<= 1) {
                        pS[ni][j] +=
                            __shfl_xor_sync(0xffffffffu, pS[ni][j], mask);
                        pQ[ni][j] +=
                            __shfl_xor_sync(0xffffffffu, pQ[ni][j], mask);
                    }
                }
            if (g == 0) {
#pragma unroll
                for (int ni = 0; ni < 4; ni++) {
                    int c = wx * 32 + ni * 8 + 2 * tig;
                    sS[wy * F + c]     = pS[ni][0];
                    sS[wy * F + c + 1] = pS[ni][1];
                    sQ[wy * F + c]     = pQ[ni][0];
                    sQ[wy * F + c + 1] = pQ[ni][1];
                }
            }
            __syncthreads();
            if (tid < F)
                atomicAdd(&g_stats[tid], sS[tid] + sS[F + tid]);
            else if (tid < 2 * F) {
                int c = tid - F;
                atomicAdd(&g_stats[F + c], sQ[c] + sQ[F + c]);
            }
        }
        __syncthreads();   // all reads of Abuf[buf]/stat done before reuse
        buf ^= 1;
    }
}

// ---------------------------------------------------------------------------
// fold: s[k] = gamma*rsqrt(var+eps), t[k] = beta - mean*s
//   g_W2p[o][k] = tf32r(W2[o][k]*s[k]);  g_b2p[o] = b2[o] + sum_k W2[o][k]*t[k]
// ---------------------------------------------------------------------------
__global__ void fold_kernel(const float* __restrict__ gamma,
                            const float* __restrict__ beta,
                            const float* __restrict__ W2,
                            const float* __restrict__ b2, float invM) {
    __shared__ float red[F];
    int o = blockIdx.x, t = threadIdx.x;  // 128 blocks x 128 threads
    float S = g_stats[t], Q = g_stats[F + t];
    float mean = S * invM;
    float var = Q * invM - mean * mean;
    float s = gamma[t] * rsqrtf(var + 1e-5f);
    float tc = beta[t] - mean * s;
    float w = W2[o * F + t];
    g_W2p[o * F + t] = tf32rf(w * s);
    red[t] = w * tc;
    __syncthreads();
#pragma unroll
    for (int off = 64; off > 0; off >>= 1) {
        if (t < off) red[t] += red[t + off];
        __syncthreads();
    }
    if (t == 0) g_b2p[o] = b2[o] + red[0];
}

// ---------------------------------------------------------------------------
extern "C" void kernel_launch(void* const* d_in, const int* in_sizes, int n_in,
                              void* d_out, int out_size) {
    const float* x         = (const float*)d_in[0];
    const void*  ei        = (const void*)d_in[1];
    const float* W1        = (const float*)d_in[2];
    const float* b1        = (const float*)d_in[3];
    const float* gamma     = (const float*)d_in[4];
    const float* beta      = (const float*)d_in[5];
    const float* W2        = (const float*)d_in[6];
    const float* b2        = (const float*)d_in[7];
    float* out             = (float*)d_out;

    int n_nodes = in_sizes[0] / F;
    int n_edges = in_sizes[1] / 2;

    cudaFuncSetAttribute(gemm_kernel<true>,
                         cudaFuncAttributeMaxDynamicSharedMemorySize, GEMM_SMEM);
    cudaFuncSetAttribute(gemm_kernel<false>,
                         cudaFuncAttributeMaxDynamicSharedMemorySize, GEMM_SMEM);

    int nsm = 148;
    cudaDeviceGetAttribute(&nsm, cudaDevAttrMultiProcessorCount, 0);
    int ntiles = (n_nodes + 63) / 64;
    int grid = nsm < ntiles ? nsm : ntiles;

    zero_kernel<<<(n_nodes + 255) / 256, 256>>>((const int*)ei, in_sizes[1],
                                                n_nodes, W1);
    convert_kernel<<<(n_edges + 255) / 256, 256>>>(ei, n_edges, n_nodes);

    int gwarps_blocks = (n_nodes * 32 + 255) / 256;
    gather_kernel<<<gwarps_blocks, 256>>>(x, n_nodes);

    gemm_kernel<true><<<grid, 256, GEMM_SMEM>>>(b1, nullptr, n_nodes, ntiles);
    fold_kernel<<<F, F>>>(gamma, beta, W2, b2, 1.0f / (float)n_nodes);
    gemm_kernel<false><<<grid, 256, GEMM_SMEM>>>(nullptr, out, n_nodes, ntiles);
}

// round 13
// speedup vs baseline: 1.1280x; 1.0032x over previous
#include <cuda_runtime.h>
#include <cuda_bf16.h>

#define MAX_NODES 50000
#define MAX_E     800000
#define F 128
#define DEG_CAP   64
#define SPILL_CAP 65536

// Scratch (device globals; allocation-free per harness rules)
__device__ __align__(16) float g_agg[MAX_NODES * F];   // tf32-rounded agg
__device__ __align__(16) float g_h[MAX_NODES * F];     // tf32-rounded hidden
__device__ __align__(16) float g_W1p[F * F];           // tf32-rounded W1
__device__ __align__(16) float g_W2p[F * F];           // BN-scaled, rounded W2
__device__ float g_stats[2 * F];       // [0:128) sum, [128:256) sumsq
__device__ float g_b2p[F];             // BN-folded bias for layer 2
__device__ int   g_cnt[MAX_NODES];     // degree per dst
__device__ int   g_csrp[MAX_NODES * DEG_CAP];  // padded CSR (12.8 MB)
__device__ int   g_spill[2 * SPILL_CAP];
__device__ int   g_nspill;
__device__ int   g_is64;

// ---------------------------------------------------------------------------
// tf32 / mma / cp.async helpers
// ---------------------------------------------------------------------------
__device__ __forceinline__ unsigned tf32r(float f) {
    unsigned u;
    asm("cvt.rna.tf32.f32 %0, %1;" : "=r"(u) : "f"(f));
    return u;
}
__device__ __forceinline__ float tf32rf(float f) {
    return __uint_as_float(tf32r(f));
}
__device__ __forceinline__ void mma_tf32(
    float& d0, float& d1, float& d2, float& d3,
    unsigned a0, unsigned a1, unsigned a2, unsigned a3,
    unsigned b0, unsigned b1) {
    asm volatile(
        "mma.sync.aligned.m16n8k8.row.col.f32.tf32.tf32.f32 "
        "{%0,%1,%2,%3},{%4,%5,%6,%7},{%8,%9},{%0,%1,%2,%3};"
        : "+f"(d0), "+f"(d1), "+f"(d2), "+f"(d3)
        : "r"(a0), "r"(a1), "r"(a2), "r"(a3), "r"(b0), "r"(b1));
}
__device__ __forceinline__ void cp16(float* dst, const float* src, bool valid) {
    unsigned sdst = (unsigned)__cvta_generic_to_shared(dst);
    int sz = valid ? 16 : 0;
    asm volatile("cp.async.ca.shared.global [%0], [%1], 16, %2;"
                 :: "r"(sdst), "l"(src), "r"(sz));
}
__device__ __forceinline__ void cp_commit() {
    asm volatile("cp.async.commit_group;" ::: "memory");
}

// ---------------------------------------------------------------------------
// zero: counters + stats + spill; block0/warp0 detects edge dtype;
// blocks [0,64) also prep tf32-rounded W1 -> g_W1p.
// ---------------------------------------------------------------------------
__global__ void zero_kernel(const int* __restrict__ ei, int n_words,
                            int n_nodes, const float* __restrict__ W1) {
    if (blockIdx.x == 0 && threadIdx.x < 32) {
        int nz = 0;
        for (int i = threadIdx.x; i < 2048; i += 32) {
            int w = 2 * i + 1;
            if (w < n_words && ei[w] != 0) nz = 1;
        }
        nz = __any_sync(0xffffffffu, nz);
        if (threadIdx.x == 0) g_is64 = nz ? 0 : 1;
    }
    if (blockIdx.x < 64) {
        int r = blockIdx.x * 2 + (threadIdx.x >> 7);
        int c = threadIdx.x & 127;
        g_W1p[r * F + c] = tf32rf(W1[r * F + c]);
    }
    int i = blockIdx.x * blockDim.x + threadIdx.x;
    if (i < n_nodes) g_cnt[i] = 0;
    if (i < 2 * F) g_stats[i] = 0.0f;
    if (i == 2 * F) g_nspill = 0;
}

// ---------------------------------------------------------------------------
// convert: unpack indices (guarded) + build padded CSR directly
// ---------------------------------------------------------------------------
__global__ void convert_kernel(const void* __restrict__ eiv, int n_edges,
                               int n_nodes) {
    int e = blockIdx.x * blockDim.x + threadIdx.x;
    if (e >= n_edges) return;
    long long s, d;
    if (g_is64) {
        const long long* ei = (const long long*)eiv;
        s = ei[e];
        d = ei[n_edges + e];
    } else {
        const int* ei = (const int*)eiv;
        s = ei[e];
        d = ei[n_edges + e];
    }
    if (s < 0 || s >= n_nodes || d < 0 || d >= n_nodes) return;
    int di = (int)d, si = (int)s;
    int c = atomicAdd(&g_cnt[di], 1);
    if (c < DEG_CAP) {
        g_csrp[di * DEG_CAP + c] = si;
    } else {
        int p = atomicAdd(&g_nspill, 1);
        if (p < SPILL_CAP) {
            g_spill[2 * p] = di;
            g_spill[2 * p + 1] = si;
        }
    }
}

// ---------------------------------------------------------------------------
// gather: agg[m] = x[m] + sum_{src in CSR[m]} x[src]; one warp per node.
// Output is tf32-rounded (gemm1 consumes it raw via cp.async).
// ---------------------------------------------------------------------------
__device__ __forceinline__ void f4add(float4& a, const float4& b) {
    a.x += b.x; a.y += b.y; a.z += b.z; a.w += b.w;
}

__global__ void __launch_bounds__(256)
gather_kernel(const float* __restrict__ Xp, int n_nodes) {
    int m = (blockIdx.x * blockDim.x + threadIdx.x) >> 5;
    int tx = threadIdx.x & 31;
    if (m >= n_nodes) return;
    const float4* x4 = (const float4*)Xp;

    float4 a0 = __ldg(&x4[(size_t)m * 32 + tx]);   // self term
    float4 a1 = make_float4(0.f, 0.f, 0.f, 0.f);
    float4 a2 = a1, a3 = a1;

    int deg = g_cnt[m];
    int dc = deg < DEG_CAP ? deg : DEG_CAP;
    const int* lst = g_csrp + (size_t)m * DEG_CAP;
    int e = 0;
    for (; e + 3 < dc; e += 4) {
        int s0 = __ldg(&lst[e]),     s1 = __ldg(&lst[e + 1]);
        int s2 = __ldg(&lst[e + 2]), s3 = __ldg(&lst[e + 3]);
        float4 v0 = __ldg(&x4[(size_t)s0 * 32 + tx]);
        float4 v1 = __ldg(&x4[(size_t)s1 * 32 + tx]);
        float4 v2 = __ldg(&x4[(size_t)s2 * 32 + tx]);
        float4 v3 = __ldg(&x4[(size_t)s3 * 32 + tx]);
        f4add(a0, v0); f4add(a1, v1); f4add(a2, v2); f4add(a3, v3);
    }
    for (; e < dc; e++)
        f4add(a1, __ldg(&x4[(size_t)__ldg(&lst[e]) * 32 + tx]));
    if (deg > DEG_CAP) {                 // spill path (normally never taken)
        int nspill = g_nspill;
        if (nspill > SPILL_CAP) nspill = SPILL_CAP;
        for (int q = 0; q < nspill; q++)
            if (g_spill[2 * q] == m)
                f4add(a2, __ldg(&x4[(size_t)g_spill[2 * q + 1] * 32 + tx]));
    }
    f4add(a0, a1); f4add(a2, a3); f4add(a0, a2);
    a0.x = tf32rf(a0.x); a0.y = tf32rf(a0.y);
    a0.z = tf32rf(a0.z); a0.w = tf32rf(a0.w);
    ((float4*)g_agg)[(size_t)m * 32 + tx] = a0;
}

// ---------------------------------------------------------------------------
// Persistent tensor-core GEMM (tf32 mma.sync), cp.async double-buffered A.
// Grid = #SMs, 1 CTA/SM, 512 threads = 16 warps as wy4 x wx4.
// Block tile 128(m) x 128(n); warp tile 32(m) x 32(n); 16 k-steps of 8.
// W (128x128, pre-rounded) loaded to smem ONCE; A double-buffered.
// FIRST: A=g_agg, W=g_W1p, bias=b1 arg; out=g_h (tf32-rounded) + BN stats.
// else:  A=g_h, W=g_W2p, bias=g_b2p; out=d_out (fp32).
// ---------------------------------------------------------------------------
#define PITCH 132
// floats: W 128*132=16896 | A0 128*132=16896 | A1 16896 | stats 1024
#define OFF_A0 16896
#define OFF_A1 33792
#define OFF_ST 50688
#define GEMM_SMEM ((50688 + 1024) * 4)
#define GTHREADS 512
#define TILE_M 128

__device__ __forceinline__ void load_W_async(float* Ws, const float* Wsrc,
                                             int tid) {
#pragma unroll
    for (int p = 0; p < 8; p++) {
        int idx = tid + p * GTHREADS;     // 16B-granule index (4096 total)
        int r = idx >> 5, c = idx & 31;
        cp16(Ws + r * PITCH + c * 4, Wsrc + r * F + c * 4, true);
    }
}
__device__ __forceinline__ void load_A_async(float* Ab, const float* Asrc,
                                             int m0, int M, int tid) {
#pragma unroll
    for (int p = 0; p < 8; p++) {
        int idx = tid + p * GTHREADS;     // 4096 granules (128 rows)
        int r = idx >> 5, c = idx & 31;
        bool v = (m0 + r) < M;
        const float* src = Asrc + (size_t)(v ? m0 + r : 0) * F + c * 4;
        cp16(Ab + r * PITCH + c * 4, src, v);
    }
}

template <bool FIRST>
__global__ void __launch_bounds__(GTHREADS, 1)
gemm_kernel(const float* __restrict__ biasp, float* __restrict__ outp,
            int M, int ntiles) {
    extern __shared__ float smem[];
    float* Ws = smem;
    float* Abuf[2] = {smem + OFF_A0, smem + OFF_A1};
    float* sS = smem + OFF_ST;          // [4][128]
    float* sQ = smem + OFF_ST + 512;    // [4][128]

    const float* A    = FIRST ? g_agg : g_h;
    const float* Wsrc = FIRST ? g_W1p : g_W2p;
    const float* bias = FIRST ? biasp : g_b2p;
    float* out        = FIRST ? g_h   : outp;

    int tid = threadIdx.x;
    int lane = tid & 31, wid = tid >> 5;
    int g = lane >> 2, tig = lane & 3;
    int wy = wid & 3, wx = wid >> 2;    // 4 x 4 warp grid, 32x32 warp tiles

    // Prologue: W + first A tile in one group
    load_W_async(Ws, Wsrc, tid);
    int t0 = blockIdx.x;
    if (t0 < ntiles) load_A_async(Abuf[0], A, t0 * TILE_M, M, tid);
    cp_commit();

    int buf = 0;
    for (int t = t0; t < ntiles; t += gridDim.x) {
        int tn = t + gridDim.x;
        bool hasNext = tn < ntiles;
        if (hasNext) {
            load_A_async(Abuf[buf ^ 1], A, tn * TILE_M, M, tid);
            cp_commit();
            asm volatile("cp.async.wait_group 1;" ::: "memory");
        } else {
            asm volatile("cp.async.wait_group 0;" ::: "memory");
        }
        __syncthreads();

        int m0 = t * TILE_M;
        float* As = Abuf[buf];

        float d[2][4][4];
#pragma unroll
        for (int mi = 0; mi < 2; mi++)
#pragma unroll
            for (int ni = 0; ni < 4; ni++)
#pragma unroll
                for (int j = 0; j < 4; j++) d[mi][ni][j] = 0.0f;

        const float* Ab = As + (wy * 32) * PITCH;
        const float* Bb = Ws + (wx * 32) * PITCH;

#pragma unroll
        for (int kk = 0; kk < 16; kk++) {
            int kc = kk * 8;
            unsigned a[2][4];
#pragma unroll
            for (int mi = 0; mi < 2; mi++) {
                const float* ap = Ab + (mi * 16 + g) * PITCH + kc + tig;
                a[mi][0] = __float_as_uint(ap[0]);
                a[mi][1] = __float_as_uint(ap[8 * PITCH]);
                a[mi][2] = __float_as_uint(ap[4]);
                a[mi][3] = __float_as_uint(ap[8 * PITCH + 4]);
            }
            unsigned b[4][2];
#pragma unroll
            for (int ni = 0; ni < 4; ni++) {
                const float* bp = Bb + (ni * 8 + g) * PITCH + kc + tig;
                b[ni][0] = __float_as_uint(bp[0]);
                b[ni][1] = __float_as_uint(bp[4]);
            }
#pragma unroll
            for (int mi = 0; mi < 2; mi++)
#pragma unroll
                for (int ni = 0; ni < 4; ni++)
                    mma_tf32(d[mi][ni][0], d[mi][ni][1], d[mi][ni][2],
                             d[mi][ni][3],
                             a[mi][0], a[mi][1], a[mi][2], a[mi][3],
                             b[ni][0], b[ni][1]);
        }

        // Epilogue: rows wy*32 + mi*16 + g (+8); cols wx*32 + ni*8 + 2*tig.
        float pS[4][2], pQ[4][2];
        if (FIRST) {
#pragma unroll
            for (int ni = 0; ni < 4; ni++) {
                pS[ni][0] = pS[ni][1] = 0.f;
                pQ[ni][0] = pQ[ni][1] = 0.f;
            }
        }
#pragma unroll
        for (int mi = 0; mi < 2; mi++) {
            int r0 = m0 + wy * 32 + mi * 16 + g;
            int r1 = r0 + 8;
#pragma unroll
            for (int ni = 0; ni < 4; ni++) {
                int c = wx * 32 + ni * 8 + 2 * tig;
                float b0 = bias[c], b1 = bias[c + 1];
                if (r0 < M) {
                    float v0 = d[mi][ni][0] + b0;
                    float v1 = d[mi][ni][1] + b1;
                    if (FIRST) {
                        v0 = fmaxf(v0, 0.f); v1 = fmaxf(v1, 0.f);
                        pS[ni][0] += v0; pS[ni][1] += v1;
                        pQ[ni][0] += v0 * v0; pQ[ni][1] += v1 * v1;
                        *(float2*)&out[(size_t)r0 * F + c] =
                            make_float2(tf32rf(v0), tf32rf(v1));
                    } else {
                        *(float2*)&out[(size_t)r0 * F + c] =
                            make_float2(v0, v1);
                    }
                }
                if (r1 < M) {
                    float v0 = d[mi][ni][2] + b0;
                    float v1 = d[mi][ni][3] + b1;
                    if (FIRST) {
                        v0 = fmaxf(v0, 0.f); v1 = fmaxf(v1, 0.f);
                        pS[ni][0] += v0; pS[ni][1] += v1;
                        pQ[ni][0] += v0 * v0; pQ[ni][1] += v1 * v1;
                        *(float2*)&out[(size_t)r1 * F + c] =
                            make_float2(tf32rf(v0), tf32rf(v1));
                    } else {
                        *(float2*)&out[(size_t)r1 * F + c] =
                            make_float2(v0, v1);
                    }
                }
            }
        }

        if (FIRST) {
#pragma unroll
            for (int ni = 0; ni < 4; ni++)
#pragma unroll
                for (int j = 0; j < 2; j++) {
#pragma unroll
                    for (int mask = 4; mask <= 16; mask <<= 1) {
                        pS[ni][j] +=
                            __shfl_xor_sync(0xffffffffu, pS[ni][j], mask);
                        pQ[ni][j] +=
                            __shfl_xor_sync(0xffffffffu, pQ[ni][j], mask);
                    }
                }
            if (g == 0) {
#pragma unroll
                for (int ni = 0; ni < 4; ni++) {
                    int c = wx * 32 + ni * 8 + 2 * tig;
                    sS[wy * F + c]     = pS[ni][0];
                    sS[wy * F + c + 1] = pS[ni][1];
                    sQ[wy * F + c]     = pQ[ni][0];
                    sQ[wy * F + c + 1] = pQ[ni][1];
                }
            }
            __syncthreads();
            if (tid < F)
                atomicAdd(&g_stats[tid],
                          sS[tid] + sS[F + tid] + sS[2 * F + tid] +
                              sS[3 * F + tid]);
            else if (tid < 2 * F) {
                int c = tid - F;
                atomicAdd(&g_stats[F + c],
                          sQ[c] + sQ[F + c] + sQ[2 * F + c] + sQ[3 * F + c]);
            }
        }
        __syncthreads();   // all reads of Abuf[buf]/stat done before reuse
        buf ^= 1;
    }
}

// ---------------------------------------------------------------------------
// fold: s[k] = gamma*rsqrt(var+eps), t[k] = beta - mean*s
//   g_W2p[o][k] = tf32r(W2[o][k]*s[k]);  g_b2p[o] = b2[o] + sum_k W2[o][k]*t[k]
// ---------------------------------------------------------------------------
__global__ void fold_kernel(const float* __restrict__ gamma,
                            const float* __restrict__ beta,
                            const float* __restrict__ W2,
                            const float* __restrict__ b2, float invM) {
    __shared__ float red[F];
    int o = blockIdx.x, t = threadIdx.x;  // 128 blocks x 128 threads
    float S = g_stats[t], Q = g_stats[F + t];
    float mean = S * invM;
    float var = Q * invM - mean * mean;
    float s = gamma[t] * rsqrtf(var + 1e-5f);
    float tc = beta[t] - mean * s;
    float w = W2[o * F + t];
    g_W2p[o * F + t] = tf32rf(w * s);
    red[t] = w * tc;
    __syncthreads();
#pragma unroll
    for (int off = 64; off > 0; off >>= 1) {
        if (t < off) red[t] += red[t + off];
        __syncthreads();
    }
    if (t == 0) g_b2p[o] = b2[o] + red[0];
}

// ---------------------------------------------------------------------------
extern "C" void kernel_launch(void* const* d_in, const int* in_sizes, int n_in,
                              void* d_out, int out_size) {
    const float* x         = (const float*)d_in[0];
    const void*  ei        = (const void*)d_in[1];
    const float* W1        = (const float*)d_in[2];
    const float* b1        = (const float*)d_in[3];
    const float* gamma     = (const float*)d_in[4];
    const float* beta      = (const float*)d_in[5];
    const float* W2        = (const float*)d_in[6];
    const float* b2        = (const float*)d_in[7];
    float* out             = (float*)d_out;

    int n_nodes = in_sizes[0] / F;
    int n_edges = in_sizes[1] / 2;

    cudaFuncSetAttribute(gemm_kernel<true>,
                         cudaFuncAttributeMaxDynamicSharedMemorySize, GEMM_SMEM);
    cudaFuncSetAttribute(gemm_kernel<false>,
                         cudaFuncAttributeMaxDynamicSharedMemorySize, GEMM_SMEM);

    int nsm = 148;
    cudaDeviceGetAttribute(&nsm, cudaDevAttrMultiProcessorCount, 0);
    int ntiles = (n_nodes + TILE_M - 1) / TILE_M;
    int grid = nsm < ntiles ? nsm : ntiles;

    zero_kernel<<<(n_nodes + 255) / 256, 256>>>((const int*)ei, in_sizes[1],
                                                n_nodes, W1);
    convert_kernel<<<(n_edges + 255) / 256, 256>>>(ei, n_edges, n_nodes);

    int gwarps_blocks = (n_nodes * 32 + 255) / 256;
    gather_kernel<<<gwarps_blocks, 256>>>(x, n_nodes);

    gemm_kernel<true><<<grid, GTHREADS, GEMM_SMEM>>>(b1, nullptr, n_nodes,
                                                     ntiles);
    fold_kernel<<<F, F>>>(gamma, beta, W2, b2, 1.0f / (float)n_nodes);
    gemm_kernel<false><<<grid, GTHREADS, GEMM_SMEM>>>(nullptr, out, n_nodes,
                                                      ntiles);
}